// round 16
// baseline (speedup 1.0000x reference)
#include <cuda_runtime.h>
#include <cuda_fp16.h>
#include <cstdint>

#define TOKENS 16384
#define DIMS   128
#define SLOTS  64

// ---------------- device globals ---------------------------------------------
__device__ __align__(16) float g_C[DIMS * SLOTS];        // C[d][m], pre-scaled
__device__ __align__(16) float g_d0[SLOTS];               // bias, pre-scaled
// B in mma-fragment order: idx = ((m*16 + nt)*4 + kp)*32 + lane ; uint4 =
// {b0(ks=2kp), b1(ks=2kp), b0(ks=2kp+1), b1(ks=2kp+1)}  (2MB)
__device__ __align__(16) uint4 g_opsF[SLOTS * 16 * 4 * 32];

// ---------------- helpers ----------------------------------------------------
__device__ __forceinline__ uint32_t smem_u32(const void* p) {
    uint32_t a;
    asm("{ .reg .u64 t; cvta.to.shared.u64 t, %1; cvt.u32.u64 %0, t; }" : "=r"(a) : "l"(p));
    return a;
}
__device__ __forceinline__ unsigned packh2(float lo, float hi) {
    unsigned u;
    asm("{ .reg .f16 l, h; cvt.rn.f16.f32 l, %1; cvt.rn.f16.f32 h, %2; mov.b32 %0, {l, h}; }"
        : "=r"(u) : "f"(lo), "f"(hi));
    return u;
}
__device__ __forceinline__ unsigned hmul2(unsigned a, unsigned b) {
    unsigned r; asm("mul.rn.f16x2 %0, %1, %2;" : "=r"(r) : "r"(a), "r"(b)); return r;
}
__device__ __forceinline__ void ldsm4(unsigned* r, uint32_t addr) {
    asm volatile("ldmatrix.sync.aligned.m8n8.x4.shared.b16 {%0,%1,%2,%3}, [%4];"
                 : "=r"(r[0]), "=r"(r[1]), "=r"(r[2]), "=r"(r[3]) : "r"(addr));
}
__device__ __forceinline__ void mma16816(float* c, const unsigned* a, unsigned b0, unsigned b1) {
    asm volatile(
        "mma.sync.aligned.m16n8k16.row.col.f32.f16.f16.f32 "
        "{%0,%1,%2,%3}, {%4,%5,%6,%7}, {%8,%9}, {%0,%1,%2,%3};"
        : "+f"(c[0]), "+f"(c[1]), "+f"(c[2]), "+f"(c[3])
        : "r"(a[0]), "r"(a[1]), "r"(a[2]), "r"(a[3]), "r"(b0), "r"(b1));
}

// ---------------- kernel A: ops -> fragment image + C/d0 precompute ----------
// blocks 0..511: one thread per fragment-uint4 (131072 total).
// blocks 512..575: C[:,m] per block.
__global__ void kA(const float* __restrict__ ops, const float* __restrict__ Wq,
                   const float* __restrict__ bq, const float* __restrict__ MK) {
    __shared__ float mk[128];
    __shared__ float part[128];
    const int b = blockIdx.x, tid = threadIdx.x;
    if (b < 512) {
        int idx = b * 256 + tid;                 // fragment id
        int l  = idx & 31;
        int kp = (idx >> 5) & 3;
        int nt = (idx >> 7) & 15;
        int m  = idx >> 11;
        int n  = nt * 8 + (l >> 2);
        int k0 = kp * 32 + (l & 3) * 2;
        const float* p = ops + (size_t)m * 16384 + n * 128;
        float2 v0 = *(const float2*)(p + k0);
        float2 v1 = *(const float2*)(p + k0 + 8);
        float2 v2 = *(const float2*)(p + k0 + 16);
        float2 v3 = *(const float2*)(p + k0 + 24);
        uint4 o;
        o.x = packh2(v0.x, v0.y);   // b0, ks = 2kp
        o.y = packh2(v1.x, v1.y);   // b1, ks = 2kp
        o.z = packh2(v2.x, v2.y);   // b0, ks = 2kp+1
        o.w = packh2(v3.x, v3.y);   // b1, ks = 2kp+1
        g_opsF[idx] = o;
    } else {
        const int m = b - 512;                   // 0..63
        if (tid < 128) mk[tid] = MK[m * 128 + tid];
        __syncthreads();
        const int d = tid & 127, half = tid >> 7;
        const int e0 = half * 64;
        float s = 0.f;
#pragma unroll 8
        for (int e = e0; e < e0 + 64; e++) s += Wq[e * 128 + d] * mk[e];
        if (half) part[d] = s;
        __syncthreads();
        const float inv = 0.08838834764831845f;
        if (!half) g_C[d * 64 + m] = (s + part[d]) * inv;
        if (tid == 0) {
            float s2 = 0.f;
#pragma unroll 8
            for (int e = 0; e < 128; e++) s2 += bq[e] * mk[e];
            g_d0[m] = s2 * inv;
        }
    }
}

// ---------------- kernel 2: fused attn + fp16 mma, B direct from gmem --------
// 148 CTAs x 512 thr (1/SM). CTA = ng*16 tokens (7 or 6 groups) x 128 dims.
// Warps 4 rows x 4 cols; row r owns groups {r, r+4}; col owns dims [32c,32c+32).
// B fragments LDG.128'd straight to registers (L1-cached 4x across row-warps).
// NO smem B, NO cp.async, NO barriers in the mainloop.
// SMEM (104896 B): AP [0,14336) | XS [14336,43008) |
//                  init-only: Cs [43008,75776), ls [75776,104896).
__global__ __launch_bounds__(512, 1) void k2_fused(const float* __restrict__ x,
                                                   float* __restrict__ out) {
    extern __shared__ __align__(16) unsigned char smraw[];
    const uint32_t SB = smem_u32(smraw);
    const uint32_t AP = SB;
    const uint32_t XS = SB + 14336u;
    float* Cs = (float*)(smraw + 43008);
    float* ls = (float*)(smraw + 75776);

    const int tid = threadIdx.x, l = tid & 31, w = tid >> 5;
    const int rowi = w >> 2, col = w & 3, wd = col * 32;
    const int cta = blockIdx.x;
    const int ng = (cta < 136) ? 7 : 6;
    const int t0 = (cta < 136) ? cta * 112 : 15232 + (cta - 136) * 96;
    const int ntok = ng * 16;

    // ---- stage x tile: fp32 -> fp16, XOR-swizzled [t][e] ----
    for (int idx = tid; idx < ntok * 16; idx += 512) {
        int row = idx >> 4, ch = idx & 15;
        const float4* sp = (const float4*)(x + (size_t)(t0 + row) * 128 + ch * 8);
        float4 v0 = sp[0], v1 = sp[1];
        uint4 o;
        o.x = packh2(v0.x, v0.y); o.y = packh2(v0.z, v0.w);
        o.z = packh2(v1.x, v1.y); o.w = packh2(v1.z, v1.w);
        asm volatile("st.shared.v4.b32 [%0], {%1,%2,%3,%4};"
                     :: "r"(XS + (unsigned)(row * 256) + (unsigned)((ch ^ (row & 7)) << 4)),
                        "r"(o.x), "r"(o.y), "r"(o.z), "r"(o.w) : "memory");
    }
    // ---- stage C (32 KB) ----
    for (int idx = tid; idx < 2048; idx += 512)
        ((float4*)Cs)[idx] = ((const float4*)g_C)[idx];
    __syncthreads();

    // ---- logits: fp32 (x from gmem, L2-hot) ----
    {
        const int t = tid >> 2, mg = tid & 3;
        if (t < ntok) {
            float acc[16];
#pragma unroll
            for (int j = 0; j < 16; j++) acc[j] = g_d0[mg * 16 + j];
            const float4* xp = (const float4*)(x + (size_t)(t0 + t) * 128);
#pragma unroll 4
            for (int d4 = 0; d4 < 32; d4++) {
                float4 xv4 = xp[d4];
                const float* cb = Cs + (d4 * 4) * 64 + mg * 16;
#pragma unroll
                for (int q = 0; q < 4; q++) {
                    float xv = (q == 0) ? xv4.x : (q == 1) ? xv4.y : (q == 2) ? xv4.z : xv4.w;
                    const float4* c4 = (const float4*)(cb + q * 64);
#pragma unroll
                    for (int j4 = 0; j4 < 4; j4++) {
                        float4 cc = c4[j4];
                        acc[j4*4+0] = fmaf(xv, cc.x, acc[j4*4+0]);
                        acc[j4*4+1] = fmaf(xv, cc.y, acc[j4*4+1]);
                        acc[j4*4+2] = fmaf(xv, cc.z, acc[j4*4+2]);
                        acc[j4*4+3] = fmaf(xv, cc.w, acc[j4*4+3]);
                    }
                }
            }
#pragma unroll
            for (int j = 0; j < 16; j++) ls[t * 65 + mg * 16 + j] = acc[j];
        }
    }
    __syncthreads();
    // ---- softmax per token ----
    if (tid < ntok) {
        float mx = -1e30f;
#pragma unroll 8
        for (int m = 0; m < 64; m++) mx = fmaxf(mx, ls[tid * 65 + m]);
        float s = 0.f;
#pragma unroll 8
        for (int m = 0; m < 64; m++) { float e = __expf(ls[tid*65+m]-mx); ls[tid*65+m] = e; s += e; }
        float iv = 1.f / s;
#pragma unroll 8
        for (int m = 0; m < 64; m++) ls[tid * 65 + m] *= iv;
    }
    __syncthreads();
    // ---- pack attn pairs (t, t+8) fp16x2 into AP [m][56] ----
    for (int idx = tid; idx < 64 * 56; idx += 512) {
        int m = idx / 56, p = idx - m * 56;
        int g = p >> 3;
        if (g < ng) {
            int tl = g * 16 + (p & 7);
            unsigned u = packh2(ls[tl * 65 + m], ls[(tl + 8) * 65 + m]);
            asm volatile("st.shared.b32 [%0], %1;" :: "r"(AP + (unsigned)idx * 4), "r"(u) : "memory");
        }
    }
    // ---- hoist group j=0 (g = rowi) A fragments to regs ----
    unsigned Areg[8][4];
    {
        const int r_off = l & 15;
        const int row = rowi * 16 + r_off;
#pragma unroll
        for (int ks = 0; ks < 8; ks++) {
            int chA = ks * 2 + (l >> 4);
            uint32_t addr = XS + row * 256 + ((chA ^ (r_off & 7)) << 4);
            ldsm4(Areg[ks], addr);
        }
    }
    __syncthreads();   // AP + XS visible everywhere; no more CTA syncs

    float acc[2][4][4] = {};
    const int g1 = rowi + 4;
    const bool has1 = (g1 < ng);
    // per-warp fragment base: + m*2048 each slot; nt local j at +j*128, kp at +kp*32
    const uint4* Bw = g_opsF + col * 512 + l;

    for (int m = 0; m < 64; m++) {
        // attn splats for this slot
        unsigned lo2[2], hi2[2];
        {
            unsigned pu;
            asm volatile("ld.shared.b32 %0, [%1];"
                         : "=r"(pu) : "r"(AP + (unsigned)(m * 56 + rowi * 8 + (l >> 2)) * 4));
            asm("prmt.b32 %0, %1, %1, 0x1010;" : "=r"(lo2[0]) : "r"(pu));
            asm("prmt.b32 %0, %1, %1, 0x3232;" : "=r"(hi2[0]) : "r"(pu));
        }
        if (has1) {
            unsigned pu;
            asm volatile("ld.shared.b32 %0, [%1];"
                         : "=r"(pu) : "r"(AP + (unsigned)(m * 56 + g1 * 8 + (l >> 2)) * 4));
            asm("prmt.b32 %0, %1, %1, 0x1010;" : "=r"(lo2[1]) : "r"(pu));
            asm("prmt.b32 %0, %1, %1, 0x3232;" : "=r"(hi2[1]) : "r"(pu));
        }

        const uint4* Bm = Bw + m * 2048;
#pragma unroll
        for (int kp = 0; kp < 4; kp++) {
            uint4 f0 = Bm[kp * 32];            // nt local 0
            uint4 f1 = Bm[128 + kp * 32];      // nt local 1
            uint4 f2 = Bm[256 + kp * 32];      // nt local 2
            uint4 f3 = Bm[384 + kp * 32];      // nt local 3
#pragma unroll
            for (int e = 0; e < 2; e++) {
                const int ks = kp * 2 + e;
                const unsigned b0[4] = { e ? f0.z : f0.x, e ? f1.z : f1.x,
                                         e ? f2.z : f2.x, e ? f3.z : f3.x };
                const unsigned b1[4] = { e ? f0.w : f0.y, e ? f1.w : f1.y,
                                         e ? f2.w : f2.y, e ? f3.w : f3.y };
                // group 0: hoisted A
                {
                    unsigned t[4];
                    t[0] = hmul2(Areg[ks][0], lo2[0]);
                    t[1] = hmul2(Areg[ks][1], hi2[0]);
                    t[2] = hmul2(Areg[ks][2], lo2[0]);
                    t[3] = hmul2(Areg[ks][3], hi2[0]);
#pragma unroll
                    for (int j = 0; j < 4; j++)
                        mma16816(acc[0][j], t, b0[j], b1[j]);
                }
                // group 1: per-slot ldsm from resident x tile
                if (has1) {
                    const int r_off = l & 15;
                    int chA = ks * 2 + (l >> 4);
                    int row = g1 * 16 + r_off;
                    uint32_t addr = XS + row * 256 + ((chA ^ (r_off & 7)) << 4);
                    unsigned a[4];
                    ldsm4(a, addr);
                    unsigned t[4];
                    t[0] = hmul2(a[0], lo2[1]);
                    t[1] = hmul2(a[1], hi2[1]);
                    t[2] = hmul2(a[2], lo2[1]);
                    t[3] = hmul2(a[3], hi2[1]);
#pragma unroll
                    for (int j = 0; j < 4; j++)
                        mma16816(acc[1][j], t, b0[j], b1[j]);
                }
            }
        }
    }

    // ---- writeback ----
#pragma unroll
    for (int j = 0; j < 2; j++) {
        int g = rowi + 4 * j;
        if (j == 0 || has1) {
            int row = t0 + g * 16 + (l >> 2);
#pragma unroll
            for (int nt = 0; nt < 4; nt++) {
                int dcol = wd + nt * 8 + (l & 3) * 2;
                *(float2*)(out + (size_t)row * 128 + dcol) =
                    make_float2(acc[j][nt][0], acc[j][nt][1]);
                *(float2*)(out + (size_t)(row + 8) * 128 + dcol) =
                    make_float2(acc[j][nt][2], acc[j][nt][3]);
            }
        }
    }
}

// ---------------------------------------------------------------------------
extern "C" void kernel_launch(void* const* d_in, const int* in_sizes, int n_in,
                              void* d_out, int out_size) {
    const float* x   = (const float*)d_in[0];   // [4,4096,128]
    const float* MK  = (const float*)d_in[1];   // [64,128]
    const float* ops = (const float*)d_in[2];   // [64,128,128]
    const float* Wq  = (const float*)d_in[3];   // [128,128]
    const float* bq  = (const float*)d_in[4];   // [128]
    float* out = (float*)d_out;

    const int smem2 = 104896;
    cudaFuncSetAttribute(k2_fused, cudaFuncAttributeMaxDynamicSharedMemorySize, smem2);

    kA<<<576, 256>>>(ops, Wq, bq, MK);
    k2_fused<<<148, 512, smem2>>>(x, out);
}

// round 17
// speedup vs baseline: 1.1599x; 1.1599x over previous
#include <cuda_runtime.h>
#include <cuda_fp16.h>
#include <cstdint>

#define TOKENS 16384
#define DIMS   128
#define SLOTS  64

// ---------------- device globals ---------------------------------------------
__device__ __align__(16) float g_C[DIMS * SLOTS];        // C[d][m], pre-scaled
__device__ __align__(16) float g_d0[SLOTS];               // bias, pre-scaled
__device__ __align__(16) unsigned g_opsH[SLOTS * DIMS * 64]; // fp16 ops, swizzled (2MB)

// ---------------- helpers ----------------------------------------------------
__device__ __forceinline__ uint32_t smem_u32(const void* p) {
    uint32_t a;
    asm("{ .reg .u64 t; cvta.to.shared.u64 t, %1; cvt.u32.u64 %0, t; }" : "=r"(a) : "l"(p));
    return a;
}
__device__ __forceinline__ unsigned packh2(float lo, float hi) {
    unsigned u;
    asm("{ .reg .f16 l, h; cvt.rn.f16.f32 l, %1; cvt.rn.f16.f32 h, %2; mov.b32 %0, {l, h}; }"
        : "=r"(u) : "f"(lo), "f"(hi));
    return u;
}
__device__ __forceinline__ unsigned hmul2(unsigned a, unsigned b) {
    unsigned r; asm("mul.rn.f16x2 %0, %1, %2;" : "=r"(r) : "r"(a), "r"(b)); return r;
}
__device__ __forceinline__ void ldsm4(unsigned* r, uint32_t addr) {
    asm volatile("ldmatrix.sync.aligned.m8n8.x4.shared.b16 {%0,%1,%2,%3}, [%4];"
                 : "=r"(r[0]), "=r"(r[1]), "=r"(r[2]), "=r"(r[3]) : "r"(addr));
}
__device__ __forceinline__ void mma16816(float* c, const unsigned* a, unsigned b0, unsigned b1) {
    asm volatile(
        "mma.sync.aligned.m16n8k16.row.col.f32.f16.f16.f32 "
        "{%0,%1,%2,%3}, {%4,%5,%6,%7}, {%8,%9}, {%0,%1,%2,%3};"
        : "+f"(c[0]), "+f"(c[1]), "+f"(c[2]), "+f"(c[3])
        : "r"(a[0]), "r"(a[1]), "r"(a[2]), "r"(a[3]), "r"(b0), "r"(b1));
}
__device__ __forceinline__ void cpasync16(uint32_t dst, const void* src) {
    asm volatile("cp.async.cg.shared.global [%0], [%1], 16;" :: "r"(dst), "l"(src) : "memory");
}

// ---------------- kernel A: ops->fp16 swizzled image + C/d0 precompute -------
__global__ void kA(const float* __restrict__ ops, const float* __restrict__ Wq,
                   const float* __restrict__ bq, const float* __restrict__ MK) {
    __shared__ float mk[128];
    __shared__ float part[128];
    const int b = blockIdx.x, tid = threadIdx.x;
    if (b < 512) {
        int idx = b * 256 + tid;                 // 16B-chunk id, 131072 total
        int m = idx >> 11, c = idx & 2047;
        int d = c >> 4, ch = c & 15;
        const float4* s = (const float4*)(ops + m * 16384 + d * 128 + ch * 8);
        float4 v0 = s[0], v1 = s[1];
        uint4 o;
        o.x = packh2(v0.x, v0.y); o.y = packh2(v0.z, v0.w);
        o.z = packh2(v1.x, v1.y); o.w = packh2(v1.z, v1.w);
        unsigned dst = (unsigned)m * 8192u + (unsigned)d * 64u
                     + (unsigned)((ch ^ (d & 7)) << 2);   // u32 units
        *(uint4*)(g_opsH + dst) = o;
    } else {
        const int m = b - 512;                   // 0..63
        if (tid < 128) mk[tid] = MK[m * 128 + tid];
        __syncthreads();
        const int d = tid & 127, half = tid >> 7;
        const int e0 = half * 64;
        float s = 0.f;
#pragma unroll 8
        for (int e = e0; e < e0 + 64; e++) s += Wq[e * 128 + d] * mk[e];
        if (half) part[d] = s;
        __syncthreads();
        const float inv = 0.08838834764831845f;
        if (!half) g_C[d * 64 + m] = (s + part[d]) * inv;
        if (tid == 0) {
            float s2 = 0.f;
#pragma unroll 8
            for (int e = 0; e < 128; e++) s2 += bq[e] * mk[e];
            g_d0[m] = s2 * inv;
        }
    }
}

// ---------------- kernel 2: fused attn + fp16 mma, LOW-REG mainloop ----------
// 148 CTAs x 512 thr (1/SM). CTA = ng*16 tokens (7 or 6 groups) x 128 dims.
// Warps 4 rows x 4 cols; row r owns groups {r, r+4}; col owns 32 dims.
// NO A-register hoist (keeps regs ~90 so ptxas can software-pipeline the
// ldsm->hmul2->mma chains itself — R6's winning property). B: 2 x 64KB
// double buffer, 2 slots/buffer, race-free wait->sync->prefetch order.
// Buffer 0 preloads before the attn prologue.
// SMEM map (174080 B):
//   AP   [0, 14336)        attn fp16x2 pairs (live whole kernel)
//   XS   [14336, 43008)    x tile fp16 swizzled (live whole kernel)
//   ring [43008, 174080)   2 x 64KB B buffers
//   init overlays INSIDE BUFFER 1 only: Cs=[108544,141312), ls=[141312,170432).
__global__ __launch_bounds__(512, 1) void k2_fused(const float* __restrict__ x,
                                                   float* __restrict__ out) {
    extern __shared__ __align__(16) unsigned char smraw[];
    const uint32_t SB = smem_u32(smraw);
    const uint32_t AP = SB;
    const uint32_t XS = SB + 14336u;
    const uint32_t BB = SB + 43008u;
    float* Cs = (float*)(smraw + 108544);         // inside buffer 1 (init phase)
    float* ls = (float*)(smraw + 141312);         // inside buffer 1 (init phase)

    const int tid = threadIdx.x, l = tid & 31, w = tid >> 5;
    const int rowi = w >> 2, wd = (w & 3) * 32;
    const int cta = blockIdx.x;
    const int ng = (cta < 136) ? 7 : 6;
    const int t0 = (cta < 136) ? cta * 112 : 15232 + (cta - 136) * 96;
    const int ntok = ng * 16;

    // ---- kick off B(slots 0,1) into buffer 0 FIRST (overlaps prologue) ----
#pragma unroll
    for (int i = 0; i < 8; i++) {
        int idx = tid + i * 512;
        cpasync16(BB + idx * 16, (const char*)g_opsH + idx * 16);
    }
    asm volatile("cp.async.commit_group;" ::: "memory");

    // ---- stage x tile: fp32 -> fp16, XOR-swizzled [t][e] ----
    for (int idx = tid; idx < ntok * 16; idx += 512) {
        int row = idx >> 4, ch = idx & 15;
        const float4* sp = (const float4*)(x + (size_t)(t0 + row) * 128 + ch * 8);
        float4 v0 = sp[0], v1 = sp[1];
        uint4 o;
        o.x = packh2(v0.x, v0.y); o.y = packh2(v0.z, v0.w);
        o.z = packh2(v1.x, v1.y); o.w = packh2(v1.z, v1.w);
        asm volatile("st.shared.v4.b32 [%0], {%1,%2,%3,%4};"
                     :: "r"(XS + (unsigned)(row * 256) + (unsigned)((ch ^ (row & 7)) << 4)),
                        "r"(o.x), "r"(o.y), "r"(o.z), "r"(o.w) : "memory");
    }
    // ---- stage C (32 KB, inside buffer 1) ----
    for (int idx = tid; idx < 2048; idx += 512)
        ((float4*)Cs)[idx] = ((const float4*)g_C)[idx];
    __syncthreads();

    // ---- logits: fp32 (x from gmem, L2-hot) ----
    {
        const int t = tid >> 2, mg = tid & 3;
        if (t < ntok) {
            float acc[16];
#pragma unroll
            for (int j = 0; j < 16; j++) acc[j] = g_d0[mg * 16 + j];
            const float4* xp = (const float4*)(x + (size_t)(t0 + t) * 128);
#pragma unroll 4
            for (int d4 = 0; d4 < 32; d4++) {
                float4 xv4 = xp[d4];
                const float* cb = Cs + (d4 * 4) * 64 + mg * 16;
#pragma unroll
                for (int q = 0; q < 4; q++) {
                    float xv = (q == 0) ? xv4.x : (q == 1) ? xv4.y : (q == 2) ? xv4.z : xv4.w;
                    const float4* c4 = (const float4*)(cb + q * 64);
#pragma unroll
                    for (int j4 = 0; j4 < 4; j4++) {
                        float4 cc = c4[j4];
                        acc[j4*4+0] = fmaf(xv, cc.x, acc[j4*4+0]);
                        acc[j4*4+1] = fmaf(xv, cc.y, acc[j4*4+1]);
                        acc[j4*4+2] = fmaf(xv, cc.z, acc[j4*4+2]);
                        acc[j4*4+3] = fmaf(xv, cc.w, acc[j4*4+3]);
                    }
                }
            }
#pragma unroll
            for (int j = 0; j < 16; j++) ls[t * 65 + mg * 16 + j] = acc[j];
        }
    }
    __syncthreads();
    // ---- softmax per token ----
    if (tid < ntok) {
        float mx = -1e30f;
#pragma unroll 8
        for (int m = 0; m < 64; m++) mx = fmaxf(mx, ls[tid * 65 + m]);
        float s = 0.f;
#pragma unroll 8
        for (int m = 0; m < 64; m++) { float e = __expf(ls[tid*65+m]-mx); ls[tid*65+m] = e; s += e; }
        float iv = 1.f / s;
#pragma unroll 8
        for (int m = 0; m < 64; m++) ls[tid * 65 + m] *= iv;
    }
    __syncthreads();
    // ---- pack attn pairs (t, t+8) fp16x2 into AP [m][56] ----
    for (int idx = tid; idx < 64 * 56; idx += 512) {
        int m = idx / 56, p = idx - m * 56;
        int g = p >> 3;
        if (g < ng) {
            int tl = g * 16 + (p & 7);
            unsigned u = packh2(ls[tl * 65 + m], ls[(tl + 8) * 65 + m]);
            asm volatile("st.shared.b32 [%0], %1;" :: "r"(AP + (unsigned)idx * 4), "r"(u) : "memory");
        }
    }
    __syncthreads();   // Cs/ls dead -> buffer 1 usable

    float acc[2][4][4] = {};
    const int g1 = rowi + 4;
    const bool has1 = (g1 < ng);

    for (int it = 0; it < 32; it++) {
        const int m0 = it * 2;
        // current pair's buffer fully loaded; previous compute finished by all
        asm volatile("cp.async.wait_group 0;" ::: "memory");
        __syncthreads();
        // now safe to overwrite the OTHER buffer (everyone done reading it)
        if (it < 31) {
            const char* src = (const char*)g_opsH + (size_t)(m0 + 2) * 32768;
            uint32_t dst = BB + (unsigned)((it + 1) & 1) * 65536u;
#pragma unroll
            for (int i = 0; i < 8; i++) {
                int idx = tid + i * 512;
                cpasync16(dst + idx * 16, src + idx * 16);
            }
            asm volatile("cp.async.commit_group;" ::: "memory");
        }

        const uint32_t BufB = BB + (unsigned)(it & 1) * 65536u;
#pragma unroll
        for (int sm = 0; sm < 2; sm++) {
            const int m = m0 + sm;
            // attn splats for this slot
            unsigned lo2[2], hi2[2];
            {
                unsigned pu;
                asm volatile("ld.shared.b32 %0, [%1];"
                             : "=r"(pu) : "r"(AP + (unsigned)(m * 56 + rowi * 8 + (l >> 2)) * 4));
                asm("prmt.b32 %0, %1, %1, 0x1010;" : "=r"(lo2[0]) : "r"(pu));
                asm("prmt.b32 %0, %1, %1, 0x3232;" : "=r"(hi2[0]) : "r"(pu));
            }
            if (has1) {
                unsigned pu;
                asm volatile("ld.shared.b32 %0, [%1];"
                             : "=r"(pu) : "r"(AP + (unsigned)(m * 56 + g1 * 8 + (l >> 2)) * 4));
                asm("prmt.b32 %0, %1, %1, 0x1010;" : "=r"(lo2[1]) : "r"(pu));
                asm("prmt.b32 %0, %1, %1, 0x3232;" : "=r"(hi2[1]) : "r"(pu));
            }

            const uint32_t Bb = BufB + (unsigned)(sm * 32768);
#pragma unroll
            for (int ks = 0; ks < 8; ks++) {
                const int c0 = ks * 2;
                unsigned bf[2][4];
                {
                    int n_off = ((l >> 4) << 3) + (l & 7);
                    int chB = c0 + ((l >> 3) & 1);
#pragma unroll
                    for (int np = 0; np < 2; np++) {
                        int row = wd + np * 16 + n_off;
                        uint32_t addr = Bb + row * 256 + ((chB ^ (row & 7)) << 4);
                        ldsm4(bf[np], addr);
                    }
                }
                const int r_off = l & 15;
                const int chA = c0 + (l >> 4);
#pragma unroll
                for (int j = 0; j < 2; j++) {
                    int g = rowi + 4 * j;
                    if (j == 0 || has1) {
                        int row = g * 16 + r_off;
                        uint32_t addr = XS + row * 256 + ((chA ^ (r_off & 7)) << 4);
                        unsigned a[4];
                        ldsm4(a, addr);
                        unsigned t[4];
                        t[0] = hmul2(a[0], lo2[j]);
                        t[1] = hmul2(a[1], hi2[j]);
                        t[2] = hmul2(a[2], lo2[j]);
                        t[3] = hmul2(a[3], hi2[j]);
#pragma unroll
                        for (int nt = 0; nt < 4; nt++)
                            mma16816(acc[j][nt], t, bf[nt >> 1][(nt & 1) * 2],
                                     bf[nt >> 1][(nt & 1) * 2 + 1]);
                    }
                }
            }
        }
    }

    // ---- writeback ----
#pragma unroll
    for (int j = 0; j < 2; j++) {
        int g = rowi + 4 * j;
        if (j == 0 || has1) {
            int row = t0 + g * 16 + (l >> 2);
#pragma unroll
            for (int nt = 0; nt < 4; nt++) {
                int col = wd + nt * 8 + (l & 3) * 2;
                *(float2*)(out + (size_t)row * 128 + col) =
                    make_float2(acc[j][nt][0], acc[j][nt][1]);
                *(float2*)(out + (size_t)(row + 8) * 128 + col) =
                    make_float2(acc[j][nt][2], acc[j][nt][3]);
            }
        }
    }
}

// ---------------------------------------------------------------------------
extern "C" void kernel_launch(void* const* d_in, const int* in_sizes, int n_in,
                              void* d_out, int out_size) {
    const float* x   = (const float*)d_in[0];   // [4,4096,128]
    const float* MK  = (const float*)d_in[1];   // [64,128]
    const float* ops = (const float*)d_in[2];   // [64,128,128]
    const float* Wq  = (const float*)d_in[3];   // [128,128]
    const float* bq  = (const float*)d_in[4];   // [128]
    float* out = (float*)d_out;

    const int smem2 = 174080;
    cudaFuncSetAttribute(k2_fused, cudaFuncAttributeMaxDynamicSharedMemorySize, smem2);

    kA<<<576, 256>>>(ops, Wq, bq, MK);
    k2_fused<<<148, 512, smem2>>>(x, out);
}